// round 11
// baseline (speedup 1.0000x reference)
#include <cuda_runtime.h>
#include <cuda_fp16.h>
#include <cstdint>

#define NN 25000
#define NE 400000
#define HD 128
#define LN_EPS 1e-5f

// ================= device scratch =================
__device__ int   g_src[NE];
__device__ int   g_dst[NE];
__device__ int   g_is64;
__device__ float g_eA[(size_t)NE * HD];
__device__ float g_eB[(size_t)NE * HD];
__device__ float g_agg[(size_t)NN * HD];
__device__ float g_x[(size_t)NN * HD];

// fp16 hi/lo weight pools, [n=128][Kpad] row-major per matrix
#define POOL_ELEMS 335872
__device__ __align__(16) __half g_wh[POOL_ELEMS];
__device__ __align__(16) __half g_wl[POOL_ELEMS];

// ================= smem layout (dynamic, bytes) =================
// 128-col tiles: 128 rows x 128 k-halves, row stride 272 B (256 + 16 pad).
// One tile (hi or lo) = 128*272 = 34816 B; a hi/lo pair = 69632 B.
// [0, 69632)       W pair (hi at 0, lo at 34816)
// [69632, 139264)  slot 0 pair
// [139264, 208896) slot 1 pair
#define LDT2     272u
#define TILE1    34816u
#define W_HI     0u
#define SL0      69632u
#define SL1      139264u
#define SMEM_DYN 208896
// f32 LN staging: floats at byte 139264, stride 130 (66560 B, fits slot1 pair)

// ================= helpers =================
__device__ __forceinline__ uint32_t smem_u32(const void* p) {
    uint32_t a;
    asm("{ .reg .u64 t; cvta.to.shared.u64 t, %1; cvt.u32.u64 %0, t; }"
        : "=r"(a) : "l"(p));
    return a;
}
__device__ __forceinline__ void ldsm4(uint32_t addr, uint32_t* r) {
    asm volatile("ldmatrix.sync.aligned.m8n8.x4.shared.b16 {%0,%1,%2,%3}, [%4];"
                 : "=r"(r[0]), "=r"(r[1]), "=r"(r[2]), "=r"(r[3]) : "r"(addr));
}
// not volatile — pure register op, scheduler may interleave
__device__ __forceinline__ void mma16816(float* d, const uint32_t* a,
                                         uint32_t b0, uint32_t b1) {
    asm("mma.sync.aligned.m16n8k16.row.col.f32.f16.f16.f32 "
        "{%0,%1,%2,%3}, {%4,%5,%6,%7}, {%8,%9}, {%0,%1,%2,%3};"
        : "+f"(d[0]), "+f"(d[1]), "+f"(d[2]), "+f"(d[3])
        : "r"(a[0]), "r"(a[1]), "r"(a[2]), "r"(a[3]), "r"(b0), "r"(b1));
}
__device__ __forceinline__ void cp16(uint32_t dst, const void* src) {
    asm volatile("cp.async.cg.shared.global [%0], [%1], 16;"
                 :: "r"(dst), "l"(src));
}
#define CP_COMMIT() asm volatile("cp.async.commit_group;")
#define CP_WAIT0()  asm volatile("cp.async.wait_group 0;" ::: "memory")
__device__ __forceinline__ void pack_pair(float a, float b, uint32_t& hi, uint32_t& lo) {
    __half ha = __float2half_rn(a), hb = __float2half_rn(b);
    float ra = a - __half2float(ha);
    float rb = b - __half2float(hb);
    __half2 H = __halves2half2(ha, hb);
    __half2 L = __floats2half2_rn(ra, rb);
    hi = *reinterpret_cast<uint32_t*>(&H);
    lo = *reinterpret_cast<uint32_t*>(&L);
}
__device__ __forceinline__ float silu(float v) {
    return __fdividef(v, 1.f + __expf(-v));   // MUFU path, ~2ulp
}

// ================= index prep =================
__global__ void detect_kernel(const int* __restrict__ raw) {
    __shared__ int cnt;
    if (threadIdx.x == 0) cnt = 0;
    __syncthreads();
    int c = 0;
    for (int t = threadIdx.x; t < 1024; t += blockDim.x)
        if (raw[2 * t + 1] != 0) c++;
    atomicAdd(&cnt, c);
    __syncthreads();
    if (threadIdx.x == 0) g_is64 = (cnt < 16) ? 1 : 0;
}
__global__ void convert_kernel(const int* __restrict__ raw) {
    int i = blockIdx.x * blockDim.x + threadIdx.x;
    if (i >= NE) return;
    int s, d;
    if (g_is64) {
        const long long* p = (const long long*)raw;
        s = (int)p[i];
        d = (int)p[NE + i];
    } else {
        s = raw[i];
        d = raw[NE + i];
    }
    if ((unsigned)s >= NN) s = 0;
    if ((unsigned)d >= NN) d = 0;
    g_src[i] = s;
    g_dst[i] = d;
}

// ================= weight split prep =================
#define NJOBS 15
struct WJob { const float* src; int Ksrc; int Kpad; int dst; };
struct WJobs { WJob j[NJOBS]; };
__global__ void conv_w_kernel(WJobs jobs) {
    WJob jb = jobs.j[blockIdx.y];
    int idx = blockIdx.x * 256 + threadIdx.x;
    if (idx >= 128 * jb.Kpad) return;
    int n = idx / jb.Kpad, k = idx % jb.Kpad;
    float v = (k < jb.Ksrc) ? jb.src[(size_t)k * 128 + n] : 0.f;
    __half h = __float2half_rn(v);
    float r = v - __half2float(h);
    g_wh[(size_t)jb.dst + (size_t)n * jb.Kpad + k] = h;
    g_wl[(size_t)jb.dst + (size_t)n * jb.Kpad + k] = __float2half_rn(r);
}

// ================= A gather: load phase =================
// 512 threads: r = t>>2, 32 floats per thread (one 128-col chunk row-quarter).
template <int MODE>
__device__ __forceinline__ void a_load(const float* __restrict__ in0,
                                       const float* __restrict__ in1,
                                       int chunk, int row0, int rows, int t,
                                       float4* v) {
    const int r = t >> 2;
    const int kh2 = (t & 3) << 5;         // 0,32,64,96
    const int row = row0 + r;
    const float* src = nullptr;
    if (MODE == 0) {
        if (kh2 == 0 && row < rows) src = in0 + (size_t)row * 16;
    } else if (MODE == 1) {
        if (chunk == 0)      src = in0 + (size_t)g_dst[row] * HD + kh2;
        else if (chunk == 1) src = in0 + (size_t)g_src[row] * HD + kh2;
        else                 src = in1 + (size_t)row * HD + kh2;
    } else {
        if (row < rows) src = (chunk ? in1 : in0) + (size_t)row * HD + kh2;
    }
#pragma unroll
    for (int g = 0; g < 8; g++) v[g] = make_float4(0.f, 0.f, 0.f, 0.f);
    if (src) {
        if (MODE == 0) {
#pragma unroll
            for (int g = 0; g < 4; g++) v[g] = *(const float4*)(src + g * 4);
        } else {
#pragma unroll
            for (int g = 0; g < 8; g++) v[g] = *(const float4*)(src + g * 4);
        }
    }
}

// A gather: pack + store phase (into slot pair)
__device__ __forceinline__ void a_store(char* sm, uint32_t slotHi, int t, const float4* v) {
    const int r = t >> 2;
    const int kh2 = (t & 3) << 5;
    const uint32_t rbase = (uint32_t)r * LDT2;
#pragma unroll
    for (int gg = 0; gg < 4; gg++) {
        uint32_t h[4], l[4];
        pack_pair(v[2 * gg].x,     v[2 * gg].y,     h[0], l[0]);
        pack_pair(v[2 * gg].z,     v[2 * gg].w,     h[1], l[1]);
        pack_pair(v[2 * gg + 1].x, v[2 * gg + 1].y, h[2], l[2]);
        pack_pair(v[2 * gg + 1].z, v[2 * gg + 1].w, h[3], l[3]);
        uint32_t off = rbase + (uint32_t)(kh2 + gg * 8) * 2u;
        *(uint4*)(sm + slotHi + off)         = make_uint4(h[0], h[1], h[2], h[3]);
        *(uint4*)(sm + slotHi + TILE1 + off) = make_uint4(l[0], l[1], l[2], l[3]);
    }
}

// W 128-col chunk via cp.async (512 threads); handles Kpad-kc < 128 (emb L1)
__device__ __forceinline__ void load_w_async(uint32_t sb, int wofs, int kc,
                                             int Kpad, int t) {
    const int n = t >> 2;
    const int kh2 = (t & 3) << 5;
    int limit = Kpad - kc;
    if (limit > 128) limit = 128;
    const __half* ph = g_wh + wofs + (size_t)n * Kpad + kc + kh2;
    const __half* pl = g_wl + wofs + (size_t)n * Kpad + kc + kh2;
    const uint32_t nb = (uint32_t)n * LDT2;
#pragma unroll
    for (int g = 0; g < 4; g++) {
        if (kh2 + g * 8 < limit) {
            uint32_t off = nb + (uint32_t)(kh2 + g * 8) * 2u;
            cp16(sb + W_HI + off, ph + g * 8);
            cp16(sb + W_HI + TILE1 + off, pl + g * 8);
        }
    }
}

// ================= warp MMA over one 128-col chunk; K16S k16 steps =================
template <int K16S>
__device__ __forceinline__ void mma_chunk(uint32_t sb, uint32_t aHi,
                                          float (&acc)[2][4][4], int m0, int n0, int lane) {
    const uint32_t aLo = aHi + TILE1;
    const uint32_t wHi = sb + W_HI;
    const uint32_t wLo = wHi + TILE1;
    const int rowA = m0 + (lane & 15);
    const int kselA = (lane >> 4) << 3;
    const uint32_t aB0 = (uint32_t)rowA * LDT2;
    const uint32_t aB1 = aB0 + 16u * LDT2;
    const int rowB = n0 + (lane & 7) + (((lane >> 4) & 1) << 3);
    const int kselB = ((lane >> 3) & 1) << 3;
#pragma unroll
    for (int ks = 0; ks < K16S; ks++) {
        const int k16 = ks * 16;
        uint32_t ah[2][4], al[2][4], bh[2][4], bl[2][4];
        uint32_t ak = (uint32_t)(k16 + kselA) * 2u;
        ldsm4(sb + aHi + aB0 + ak, ah[0]);
        ldsm4(sb + aHi + aB1 + ak, ah[1]);
        ldsm4(sb + aLo + aB0 + ak, al[0]);
        ldsm4(sb + aLo + aB1 + ak, al[1]);
        uint32_t bk = (uint32_t)(k16 + kselB) * 2u;
#pragma unroll
        for (int nb = 0; nb < 2; nb++) {
            uint32_t bb = (uint32_t)(rowB + nb * 16) * LDT2;
            ldsm4(wHi + bb + bk, bh[nb]);
            ldsm4(wLo + bb + bk, bl[nb]);
        }
        // pass 1: Ah x Wh
#pragma unroll
        for (int mi = 0; mi < 2; mi++)
#pragma unroll
            for (int nb = 0; nb < 2; nb++) {
                mma16816(acc[mi][nb * 2],     ah[mi], bh[nb][0], bh[nb][1]);
                mma16816(acc[mi][nb * 2 + 1], ah[mi], bh[nb][2], bh[nb][3]);
            }
        // pass 2: Al x Wh
#pragma unroll
        for (int mi = 0; mi < 2; mi++)
#pragma unroll
            for (int nb = 0; nb < 2; nb++) {
                mma16816(acc[mi][nb * 2],     al[mi], bh[nb][0], bh[nb][1]);
                mma16816(acc[mi][nb * 2 + 1], al[mi], bh[nb][2], bh[nb][3]);
            }
        // pass 3: Ah x Wl
#pragma unroll
        for (int mi = 0; mi < 2; mi++)
#pragma unroll
            for (int nb = 0; nb < 2; nb++) {
                mma16816(acc[mi][nb * 2],     ah[mi], bl[nb][0], bl[nb][1]);
                mma16816(acc[mi][nb * 2 + 1], ah[mi], bl[nb][2], bl[nb][3]);
            }
    }
}

__device__ __forceinline__ void zero_acc(float (&acc)[2][4][4]) {
#pragma unroll
    for (int mi = 0; mi < 2; mi++)
#pragma unroll
        for (int j = 0; j < 4; j++)
#pragma unroll
            for (int e = 0; e < 4; e++) acc[mi][j][e] = 0.f;
}

// ================= epilogues =================
// SiLU -> hi/lo tiles of the given slot (full 128-col tile)
__device__ __forceinline__ void epi_silu(char* sm, float (&acc)[2][4][4],
                                         const float* __restrict__ bias,
                                         uint32_t slotHi, int m0, int n0, int lane) {
    const int cq = (lane & 3) << 1;
    const int r0l = lane >> 2;
#pragma unroll
    for (int mi = 0; mi < 2; mi++)
#pragma unroll
        for (int j = 0; j < 4; j++) {
            int c = n0 + j * 8 + cq;
            float b0 = bias[c], b1 = bias[c + 1];
#pragma unroll
            for (int h = 0; h < 2; h++) {
                float v0 = silu(acc[mi][j][2 * h] + b0);
                float v1 = silu(acc[mi][j][2 * h + 1] + b1);
                uint32_t hi, lo;
                pack_pair(v0, v1, hi, lo);
                int r = m0 + mi * 16 + r0l + 8 * h;
                uint32_t off = (uint32_t)r * LDT2 + (uint32_t)(c * 2);
                *(uint32_t*)(sm + slotHi + off)         = hi;
                *(uint32_t*)(sm + slotHi + TILE1 + off) = lo;
            }
        }
}

__device__ __forceinline__ void epi_ln(char* sm, float (&acc)[2][4][4],
                                       const float* __restrict__ bias,
                                       const float* __restrict__ gam,
                                       const float* __restrict__ bet,
                                       float (*sRed)[128][2],
                                       int m0, int n0, int wn, int lane) {
    const int cq = (lane & 3) << 1;
    const int r0l = lane >> 2;
    float s[2][2] = {{0.f, 0.f}, {0.f, 0.f}};
    float q[2][2] = {{0.f, 0.f}, {0.f, 0.f}};
#pragma unroll
    for (int mi = 0; mi < 2; mi++)
#pragma unroll
        for (int j = 0; j < 4; j++) {
            int c = n0 + j * 8 + cq;
            float b0 = bias[c], b1 = bias[c + 1];
#pragma unroll
            for (int h = 0; h < 2; h++) {
                float v0 = acc[mi][j][2 * h] + b0;
                float v1 = acc[mi][j][2 * h + 1] + b1;
                s[mi][h] += v0 + v1;
                q[mi][h] += v0 * v0 + v1 * v1;
            }
        }
#pragma unroll
    for (int o = 1; o <= 2; o <<= 1)
#pragma unroll
        for (int mi = 0; mi < 2; mi++)
#pragma unroll
            for (int h = 0; h < 2; h++) {
                s[mi][h] += __shfl_xor_sync(0xffffffffu, s[mi][h], o);
                q[mi][h] += __shfl_xor_sync(0xffffffffu, q[mi][h], o);
            }
    if ((lane & 3) == 0) {
#pragma unroll
        for (int mi = 0; mi < 2; mi++)
#pragma unroll
            for (int h = 0; h < 2; h++) {
                int r = m0 + mi * 16 + r0l + 8 * h;
                sRed[wn][r][0] = s[mi][h];
                sRed[wn][r][1] = q[mi][h];
            }
    }
    __syncthreads();
    float mu[2][2], rs[2][2];
#pragma unroll
    for (int mi = 0; mi < 2; mi++)
#pragma unroll
        for (int h = 0; h < 2; h++) {
            int r = m0 + mi * 16 + r0l + 8 * h;
            float S = sRed[0][r][0] + sRed[1][r][0] + sRed[2][r][0] + sRed[3][r][0];
            float Q = sRed[0][r][1] + sRed[1][r][1] + sRed[2][r][1] + sRed[3][r][1];
            float m = S * (1.f / HD);
            float var = Q * (1.f / HD) - m * m;
            mu[mi][h] = m;
            rs[mi][h] = rsqrtf(var + LN_EPS);
        }
    float* so = (float*)(sm + SL1);  // stride 130 floats, 66560 B within slot1 pair
#pragma unroll
    for (int mi = 0; mi < 2; mi++)
#pragma unroll
        for (int j = 0; j < 4; j++) {
            int c = n0 + j * 8 + cq;
            float b0 = bias[c], b1 = bias[c + 1];
            float g0 = gam[c], g1 = gam[c + 1];
            float e0 = bet[c], e1 = bet[c + 1];
#pragma unroll
            for (int h = 0; h < 2; h++) {
                int r = m0 + mi * 16 + r0l + 8 * h;
                float v0 = acc[mi][j][2 * h] + b0;
                float v1 = acc[mi][j][2 * h + 1] + b1;
                so[r * 130 + c]     = (v0 - mu[mi][h]) * rs[mi][h] * g0 + e0;
                so[r * 130 + c + 1] = (v1 - mu[mi][h]) * rs[mi][h] * g1 + e1;
            }
        }
}

// ================= fused MLP kernel (512 threads, 128-col chunks) =================
// NCH2: 128-col layer-1 chunks; K16S1: k16 steps in each layer-1 chunk
template <int MODE, int NCH2, int K16S1>
__global__ __launch_bounds__(512, 1) void mma_mlp(
    const float* __restrict__ in0, const float* __restrict__ in1,
    int o1, int o2, int o3, int Kpad1,
    const float* __restrict__ b1, const float* __restrict__ b2,
    const float* __restrict__ b3, const float* __restrict__ gam,
    const float* __restrict__ bet,
    const float* __restrict__ resid, float* __restrict__ out, int rows) {
    extern __shared__ char sm[];
    __shared__ float sRed[4][128][2];
    const int t = threadIdx.x;
    const uint32_t sb = smem_u32(sm);
    const int lane = t & 31, w = t >> 5;
    const int m0 = (w & 3) * 32, n0 = (w >> 2) * 32, wn = w >> 2;
    const int row0 = blockIdx.x * 128;
    float acc[2][4][4];
    float4 v[8];

    // ---- layer 1: serialized 128-col chunks; W cp.async overlaps gather LDGs ----
    zero_acc(acc);
    for (int c = 0; c < NCH2; c++) {
        __syncthreads();                       // W + slot0 free
        a_load<MODE>(in0, in1, c, row0, rows, t, v);
        load_w_async(sb, o1, c * 128, Kpad1, t);
        CP_COMMIT();
        CP_WAIT0();
        a_store((char*)sm, SL0, t, v);
        __syncthreads();                       // A + W visible
        mma_chunk<K16S1>(sb, SL0, acc, m0, n0, lane);
    }
    __syncthreads();

    // ---- layer 2: H1 in slot1, single 128-chunk ----
    load_w_async(sb, o2, 0, 128, t);
    CP_COMMIT();
    epi_silu((char*)sm, acc, b1, SL1, m0, n0, lane);
    zero_acc(acc);
    CP_WAIT0();
    __syncthreads();
    mma_chunk<8>(sb, SL1, acc, m0, n0, lane);
    __syncthreads();

    // ---- layer 3: H2 in slot0 ----
    load_w_async(sb, o3, 0, 128, t);
    CP_COMMIT();
    epi_silu((char*)sm, acc, b2, SL0, m0, n0, lane);
    zero_acc(acc);
    CP_WAIT0();
    __syncthreads();
    mma_chunk<8>(sb, SL0, acc, m0, n0, lane);
    __syncthreads();
    epi_ln((char*)sm, acc, b3, gam, bet, sRed, m0, n0, wn, lane);
    __syncthreads();

    // ---- residual + coalesced store ----
    const float* so = (const float*)(sm + SL1);
    const int col = t & 127;
    for (int r = (t >> 7); r < 128; r += 4) {
        int row = row0 + r;
        if (row < rows) {
            float y = so[r * 130 + col];
            if (MODE != 0) y += resid[(size_t)row * HD + col];
            out[(size_t)row * HD + col] = y;
        }
    }
}

// ================= aggregation =================
__global__ void zero_agg_kernel() {
    size_t i = (size_t)blockIdx.x * blockDim.x + threadIdx.x;
    if (i < (size_t)NN * HD) g_agg[i] = 0.f;
}
__global__ void scatter_kernel(const float* __restrict__ e) {
    size_t i = (size_t)blockIdx.x * blockDim.x + threadIdx.x;
    if (i >= (size_t)NE * (HD / 4)) return;
    int edge = (int)(i >> 5);
    int c = (int)(i & 31) << 2;
    float4 val = *(const float4*)(e + (size_t)edge * HD + c);
    float* p = g_agg + (size_t)g_dst[edge] * HD + c;
    asm volatile("red.global.add.v4.f32 [%0], {%1, %2, %3, %4};"
                 :: "l"(p), "f"(val.x), "f"(val.y), "f"(val.z), "f"(val.w)
                 : "memory");
}

// ================= launch =================
extern "C" void kernel_launch(void* const* d_in, const int* in_sizes, int n_in,
                              void* d_out, int out_size) {
    const float* x_in    = (const float*)d_in[0];
    const int*   eidx    = (const int*)d_in[1];
    const float* eattr   = (const float*)d_in[2];
    const float* emb_W1  = (const float*)d_in[3];
    const float* emb_b1  = (const float*)d_in[4];
    const float* emb_W2  = (const float*)d_in[5];
    const float* emb_b2  = (const float*)d_in[6];
    const float* emb_W3  = (const float*)d_in[7];
    const float* emb_b3  = (const float*)d_in[8];
    const float* emb_g   = (const float*)d_in[9];
    const float* emb_be  = (const float*)d_in[10];
    const float* edge_W1 = (const float*)d_in[11];
    const float* edge_b1 = (const float*)d_in[12];
    const float* edge_W2 = (const float*)d_in[13];
    const float* edge_b2 = (const float*)d_in[14];
    const float* edge_W3 = (const float*)d_in[15];
    const float* edge_b3 = (const float*)d_in[16];
    const float* edge_g  = (const float*)d_in[17];
    const float* edge_be = (const float*)d_in[18];
    const float* node_W1 = (const float*)d_in[19];
    const float* node_b1 = (const float*)d_in[20];
    const float* node_W2 = (const float*)d_in[21];
    const float* node_b2 = (const float*)d_in[22];
    const float* node_W3 = (const float*)d_in[23];
    const float* node_b3 = (const float*)d_in[24];
    const float* node_g  = (const float*)d_in[25];
    const float* node_be = (const float*)d_in[26];

    float* out_x = (float*)d_out;
    float* out_e = (float*)d_out + (size_t)NN * HD;

    float *eA, *eB, *agg, *xbuf;
    cudaGetSymbolAddress((void**)&eA, g_eA);
    cudaGetSymbolAddress((void**)&eB, g_eB);
    cudaGetSymbolAddress((void**)&agg, g_agg);
    cudaGetSymbolAddress((void**)&xbuf, g_x);

    cudaFuncSetAttribute((const void*)mma_mlp<0, 1, 1>, cudaFuncAttributeMaxDynamicSharedMemorySize, SMEM_DYN);
    cudaFuncSetAttribute((const void*)mma_mlp<1, 3, 8>, cudaFuncAttributeMaxDynamicSharedMemorySize, SMEM_DYN);
    cudaFuncSetAttribute((const void*)mma_mlp<2, 2, 8>, cudaFuncAttributeMaxDynamicSharedMemorySize, SMEM_DYN);

    // index prep (clamped)
    detect_kernel<<<1, 256>>>(eidx);
    convert_kernel<<<(NE + 255) / 256, 256>>>(eidx);

    // pool offsets (elements)
    const int oEmb1 = 0, oEmb2 = 8192, oEmb3 = 24576;
    int oE1[2], oE2[2], oE3[2], oN1[2], oN2[2], oN3[2];
    int base = 40960;
    for (int l = 0; l < 2; l++) {
        oE1[l] = base;
        oE2[l] = base + 49152;
        oE3[l] = base + 65536;
        oN1[l] = base + 81920;
        oN2[l] = base + 114688;
        oN3[l] = base + 131072;
        base += 147456;
    }

    WJobs jobs;
    int ji = 0;
    jobs.j[ji++] = {emb_W1, 16, 16, oEmb1};   // exact K=16
    jobs.j[ji++] = {emb_W2, 128, 128, oEmb2};
    jobs.j[ji++] = {emb_W3, 128, 128, oEmb3};
    for (int l = 0; l < 2; l++) {
        jobs.j[ji++] = {edge_W1 + (size_t)l * 3 * HD * HD, 384, 384, oE1[l]};
        jobs.j[ji++] = {edge_W2 + (size_t)l * HD * HD, 128, 128, oE2[l]};
        jobs.j[ji++] = {edge_W3 + (size_t)l * HD * HD, 128, 128, oE3[l]};
        jobs.j[ji++] = {node_W1 + (size_t)l * 2 * HD * HD, 256, 256, oN1[l]};
        jobs.j[ji++] = {node_W2 + (size_t)l * HD * HD, 128, 128, oN2[l]};
        jobs.j[ji++] = {node_W3 + (size_t)l * HD * HD, 128, 128, oN3[l]};
    }
    dim3 cg((128 * 384 + 255) / 256, NJOBS);
    conv_w_kernel<<<cg, 256>>>(jobs);

    const int edge_blocks = NE / 128;           // 3125
    const int node_blocks = (NN + 127) / 128;   // 196
    const int scat_blocks = (int)(((size_t)NE * (HD / 4) + 255) / 256);
    const int nthr_blocks = (int)(((size_t)NN * HD + 255) / 256);

    // edge embedding: e = MLP(edge_attr)
    mma_mlp<0, 1, 1><<<edge_blocks, 512, SMEM_DYN>>>(
        eattr, nullptr, oEmb1, oEmb2, oEmb3, 16,
        emb_b1, emb_b2, emb_b3, emb_g, emb_be, nullptr, eA, NE);

    const float* x_cur = x_in;
    float* e_cur = eA;
    for (int l = 0; l < 2; l++) {
        float* e_out = (l == 0) ? eB : out_e;
        float* x_out = (l == 0) ? xbuf : out_x;

        // e_new = MLP([x[dst] | x[src] | e]) + e   (chunks map 1:1 to sections)
        mma_mlp<1, 3, 8><<<edge_blocks, 512, SMEM_DYN>>>(
            x_cur, e_cur, oE1[l], oE2[l], oE3[l], 384,
            edge_b1 + l * HD, edge_b2 + l * HD, edge_b3 + l * HD,
            edge_g + l * HD, edge_be + l * HD, e_cur, e_out, NE);

        // agg = segment_sum(e_new, dst)
        zero_agg_kernel<<<nthr_blocks, 256>>>();
        scatter_kernel<<<scat_blocks, 256>>>(e_out);

        // x = MLP([x | agg]) + x
        mma_mlp<2, 2, 8><<<node_blocks, 512, SMEM_DYN>>>(
            x_cur, agg, oN1[l], oN2[l], oN3[l], 256,
            node_b1 + l * HD, node_b2 + l * HD, node_b3 + l * HD,
            node_g + l * HD, node_be + l * HD, x_cur, x_out, NN);

        e_cur = e_out;
        x_cur = x_out;
    }
}

// round 12
// speedup vs baseline: 1.3209x; 1.3209x over previous
#include <cuda_runtime.h>
#include <cuda_fp16.h>
#include <cstdint>

#define NN 25000
#define NE 400000
#define HD 128
#define LN_EPS 1e-5f

// ================= device scratch =================
__device__ int   g_src[NE];
__device__ int   g_dst[NE];
__device__ int   g_is64;
__device__ float g_eA[(size_t)NE * HD];
__device__ float g_eB[(size_t)NE * HD];
__device__ float g_agg[(size_t)NN * HD];
__device__ float g_x[(size_t)NN * HD];

// fp16 hi/lo weight pools, [n=128][Kpad] row-major per matrix
#define POOL_ELEMS 335872
__device__ __align__(16) __half g_wh[POOL_ELEMS];
__device__ __align__(16) __half g_wl[POOL_ELEMS];

// ================= smem layout (dynamic, bytes) =================
// M=256 rows per CTA. 64-col tiles, row stride 144 B.
// W tile (128 n-rows): hi 18432 B, pair 36864. Double buffer: WB(0), WB(1).
// A/H slot (256 rows): hi 36864 B, pair 73728. Two slots SL(0), SL(1).
#define LDT      144u
#define WB(i)    ((uint32_t)(i) * 36864u)              // [0, 73728)
#define SL(i)    (73728u + (uint32_t)(i) * 73728u)     // [73728, 221184)
#define A_PAIR   36864u
#define W_PAIR   18432u
#define SMEM_DYN 221184
#define ROWS_CTA 256
// f32 LN staging: floats at byte 73728, stride 130 (256*130*4 = 133120 B fits)

// ================= helpers =================
__device__ __forceinline__ uint32_t smem_u32(const void* p) {
    uint32_t a;
    asm("{ .reg .u64 t; cvta.to.shared.u64 t, %1; cvt.u32.u64 %0, t; }"
        : "=r"(a) : "l"(p));
    return a;
}
__device__ __forceinline__ void ldsm4(uint32_t addr, uint32_t* r) {
    asm volatile("ldmatrix.sync.aligned.m8n8.x4.shared.b16 {%0,%1,%2,%3}, [%4];"
                 : "=r"(r[0]), "=r"(r[1]), "=r"(r[2]), "=r"(r[3]) : "r"(addr));
}
__device__ __forceinline__ void mma16816(float* d, const uint32_t* a,
                                         uint32_t b0, uint32_t b1) {
    asm("mma.sync.aligned.m16n8k16.row.col.f32.f16.f16.f32 "
        "{%0,%1,%2,%3}, {%4,%5,%6,%7}, {%8,%9}, {%0,%1,%2,%3};"
        : "+f"(d[0]), "+f"(d[1]), "+f"(d[2]), "+f"(d[3])
        : "r"(a[0]), "r"(a[1]), "r"(a[2]), "r"(a[3]), "r"(b0), "r"(b1));
}
__device__ __forceinline__ void cp16(uint32_t dst, const void* src) {
    asm volatile("cp.async.cg.shared.global [%0], [%1], 16;"
                 :: "r"(dst), "l"(src));
}
#define CP_COMMIT() asm volatile("cp.async.commit_group;")
#define CP_WAIT0()  asm volatile("cp.async.wait_group 0;" ::: "memory")
__device__ __forceinline__ void pack_pair(float a, float b, uint32_t& hi, uint32_t& lo) {
    __half ha = __float2half_rn(a), hb = __float2half_rn(b);
    float ra = a - __half2float(ha);
    float rb = b - __half2float(hb);
    __half2 H = __halves2half2(ha, hb);
    __half2 L = __floats2half2_rn(ra, rb);
    hi = *reinterpret_cast<uint32_t*>(&H);
    lo = *reinterpret_cast<uint32_t*>(&L);
}
__device__ __forceinline__ float silu(float v) {
    return __fdividef(v, 1.f + __expf(-v));
}

// ================= index prep =================
__global__ void detect_kernel(const int* __restrict__ raw) {
    __shared__ int cnt;
    if (threadIdx.x == 0) cnt = 0;
    __syncthreads();
    int c = 0;
    for (int t = threadIdx.x; t < 1024; t += blockDim.x)
        if (raw[2 * t + 1] != 0) c++;
    atomicAdd(&cnt, c);
    __syncthreads();
    if (threadIdx.x == 0) g_is64 = (cnt < 16) ? 1 : 0;
}
__global__ void convert_kernel(const int* __restrict__ raw) {
    int i = blockIdx.x * blockDim.x + threadIdx.x;
    if (i >= NE) return;
    int s, d;
    if (g_is64) {
        const long long* p = (const long long*)raw;
        s = (int)p[i];
        d = (int)p[NE + i];
    } else {
        s = raw[i];
        d = raw[NE + i];
    }
    if ((unsigned)s >= NN) s = 0;
    if ((unsigned)d >= NN) d = 0;
    g_src[i] = s;
    g_dst[i] = d;
}

// ================= weight split prep =================
#define NJOBS 15
struct WJob { const float* src; int Ksrc; int Kpad; int dst; };
struct WJobs { WJob j[NJOBS]; };
__global__ void conv_w_kernel(WJobs jobs) {
    WJob jb = jobs.j[blockIdx.y];
    int idx = blockIdx.x * 256 + threadIdx.x;
    if (idx >= 128 * jb.Kpad) return;
    int n = idx / jb.Kpad, k = idx % jb.Kpad;
    float v = (k < jb.Ksrc) ? jb.src[(size_t)k * 128 + n] : 0.f;
    __half h = __float2half_rn(v);
    float r = v - __half2float(h);
    g_wh[(size_t)jb.dst + (size_t)n * jb.Kpad + k] = h;
    g_wl[(size_t)jb.dst + (size_t)n * jb.Kpad + k] = __float2half_rn(r);
}

// ================= A gather (one 128-row half of the 256-row tile) =================
// 512 threads: r = (t>>2) + half*128, kh = (t&3)*16 halves of one 64-col chunk.
template <int MODE>
__device__ __forceinline__ void a_load(const float* __restrict__ in0,
                                       const float* __restrict__ in1,
                                       int chunk, int half, int row0, int rows,
                                       int t, float4* v) {
    const int r = (t >> 2) + half * 128;
    const int kh = (t & 3) << 4;          // 0,16,32,48
    const int gk = chunk * 64 + kh;
    const int row = row0 + r;
    const float* src = nullptr;
    if (MODE == 0) {
        if (kh == 0 && row < rows) src = in0 + (size_t)row * 16;
    } else if (MODE == 1) {
        if (row < rows) {
            int sect = gk >> 7;
            int coff = gk & 127;
            if (sect == 0)      src = in0 + (size_t)g_dst[row] * HD + coff;
            else if (sect == 1) src = in0 + (size_t)g_src[row] * HD + coff;
            else                src = in1 + (size_t)row * HD + coff;
        }
    } else {
        if (row < rows) {
            int sect = gk >> 7;
            int coff = gk & 127;
            src = (sect ? in1 : in0) + (size_t)row * HD + coff;
        }
    }
    v[0] = v[1] = v[2] = v[3] = make_float4(0.f, 0.f, 0.f, 0.f);
    if (src) {
        v[0] = *(const float4*)(src);
        v[1] = *(const float4*)(src + 4);
        v[2] = *(const float4*)(src + 8);
        v[3] = *(const float4*)(src + 12);
    }
}

__device__ __forceinline__ void a_store(char* sm, uint32_t slotHi, int half,
                                        int t, const float4* v) {
    const int r = (t >> 2) + half * 128;
    const int kh = (t & 3) << 4;
    const uint32_t rbase = (uint32_t)r * LDT;
#pragma unroll
    for (int g = 0; g < 2; g++) {
        uint32_t h[4], l[4];
        pack_pair(v[2 * g].x,     v[2 * g].y,     h[0], l[0]);
        pack_pair(v[2 * g].z,     v[2 * g].w,     h[1], l[1]);
        pack_pair(v[2 * g + 1].x, v[2 * g + 1].y, h[2], l[2]);
        pack_pair(v[2 * g + 1].z, v[2 * g + 1].w, h[3], l[3]);
        uint32_t off = rbase + (uint32_t)(kh + g * 8) * 2u;
        *(uint4*)(sm + slotHi + off)          = make_uint4(h[0], h[1], h[2], h[3]);
        *(uint4*)(sm + slotHi + A_PAIR + off) = make_uint4(l[0], l[1], l[2], l[3]);
    }
}

// W tile (128 n x 64 k) via cp.async; Kpad may be < 64 (emb L1)
__device__ __forceinline__ void load_w_async(uint32_t sb, uint32_t wb,
                                             int wofs, int kc, int Kpad, int t) {
    const int n = t >> 2;
    const int kh = (t & 3) << 4;
    if (n >= 128) return;                 // threads 512.. none (t<512, n<128 ✓)
    if (kh >= Kpad) return;               // emb L1: Kpad=16
    const __half* ph = g_wh + wofs + (size_t)n * Kpad + kc + kh;
    const __half* pl = g_wl + wofs + (size_t)n * Kpad + kc + kh;
    const uint32_t nb = (uint32_t)n * LDT;
#pragma unroll
    for (int g = 0; g < 2; g++) {
        uint32_t off = nb + (uint32_t)(kh + g * 8) * 2u;
        cp16(sb + wb + off, ph + g * 8);
        cp16(sb + wb + W_PAIR + off, pl + g * 8);
    }
}

// ================= warp MMA: 32(M) x 64(N) tile over one 64-col chunk =================
// (fragment mapping identical to proven R8 code)
template <int K16S>
__device__ __forceinline__ void mma_chunk(uint32_t sb, uint32_t aHi, uint32_t wB,
                                          float (&acc)[2][8][4], int m0, int n0, int lane) {
    const uint32_t aLo = aHi + A_PAIR;
    const uint32_t wLo = wB + W_PAIR;
    const int rowA = m0 + (lane & 15);
    const int kselA = (lane >> 4) << 3;
    const uint32_t aB0 = (uint32_t)rowA * LDT;
    const uint32_t aB1 = aB0 + 16u * LDT;
    const int rowB = n0 + (lane & 7) + (((lane >> 4) & 1) << 3);
    const int kselB = ((lane >> 3) & 1) << 3;
#pragma unroll
    for (int ks = 0; ks < K16S; ks++) {
        const int k16 = ks * 16;
        uint32_t ah[2][4], al[2][4];
        uint32_t ak = (uint32_t)(k16 + kselA) * 2u;
        ldsm4(sb + aHi + aB0 + ak, ah[0]);
        ldsm4(sb + aHi + aB1 + ak, ah[1]);
        ldsm4(sb + aLo + aB0 + ak, al[0]);
        ldsm4(sb + aLo + aB1 + ak, al[1]);
        uint32_t bk = (uint32_t)(k16 + kselB) * 2u;
#pragma unroll
        for (int nb = 0; nb < 4; nb++) {
            uint32_t bh[4], bl[4];
            uint32_t bb = (uint32_t)(rowB + nb * 16) * LDT;
            ldsm4(sb + wB + bb + bk, bh);
            ldsm4(sb + wLo + bb + bk, bl);
            // pass-major within this nb block (independent acc regs across mi/j)
#pragma unroll
            for (int mi = 0; mi < 2; mi++) {
                mma16816(acc[mi][nb * 2],     ah[mi], bh[0], bh[1]);
                mma16816(acc[mi][nb * 2 + 1], ah[mi], bh[2], bh[3]);
            }
#pragma unroll
            for (int mi = 0; mi < 2; mi++) {
                mma16816(acc[mi][nb * 2],     al[mi], bh[0], bh[1]);
                mma16816(acc[mi][nb * 2 + 1], al[mi], bh[2], bh[3]);
            }
#pragma unroll
            for (int mi = 0; mi < 2; mi++) {
                mma16816(acc[mi][nb * 2],     ah[mi], bl[0], bl[1]);
                mma16816(acc[mi][nb * 2 + 1], ah[mi], bl[2], bl[3]);
            }
        }
    }
}

__device__ __forceinline__ void zero_acc(float (&acc)[2][8][4]) {
#pragma unroll
    for (int mi = 0; mi < 2; mi++)
#pragma unroll
        for (int j = 0; j < 8; j++)
#pragma unroll
            for (int e = 0; e < 4; e++) acc[mi][j][e] = 0.f;
}

// ================= epilogues =================
// SiLU -> H slots: cols 0-63 -> SL(0), 64-127 -> SL(1)
__device__ __forceinline__ void epi_silu(char* sm, float (&acc)[2][8][4],
                                         const float* __restrict__ bias,
                                         int m0, int n0, int lane) {
    const int cq = (lane & 3) << 1;
    const int r0l = lane >> 2;
#pragma unroll
    for (int mi = 0; mi < 2; mi++)
#pragma unroll
        for (int j = 0; j < 8; j++) {
            int c = n0 + j * 8 + cq;
            float b0 = bias[c], b1 = bias[c + 1];
            uint32_t hiT = SL(c >> 6);
            int hc = c & 63;
#pragma unroll
            for (int h = 0; h < 2; h++) {
                float v0 = silu(acc[mi][j][2 * h] + b0);
                float v1 = silu(acc[mi][j][2 * h + 1] + b1);
                uint32_t hi, lo;
                pack_pair(v0, v1, hi, lo);
                int r = m0 + mi * 16 + r0l + 8 * h;
                uint32_t off = (uint32_t)r * LDT + (uint32_t)(hc * 2);
                *(uint32_t*)(sm + hiT + off)          = hi;
                *(uint32_t*)(sm + hiT + A_PAIR + off) = lo;
            }
        }
}

__device__ __forceinline__ void epi_ln(char* sm, float (&acc)[2][8][4],
                                       const float* __restrict__ bias,
                                       const float* __restrict__ gam,
                                       const float* __restrict__ bet,
                                       float (*sRed)[ROWS_CTA][2],
                                       int m0, int n0, int wn, int lane) {
    const int cq = (lane & 3) << 1;
    const int r0l = lane >> 2;
    float s[2][2] = {{0.f, 0.f}, {0.f, 0.f}};
    float q[2][2] = {{0.f, 0.f}, {0.f, 0.f}};
#pragma unroll
    for (int mi = 0; mi < 2; mi++)
#pragma unroll
        for (int j = 0; j < 8; j++) {
            int c = n0 + j * 8 + cq;
            float b0 = bias[c], b1 = bias[c + 1];
#pragma unroll
            for (int h = 0; h < 2; h++) {
                float v0 = acc[mi][j][2 * h] + b0;
                float v1 = acc[mi][j][2 * h + 1] + b1;
                s[mi][h] += v0 + v1;
                q[mi][h] += v0 * v0 + v1 * v1;
            }
        }
#pragma unroll
    for (int o = 1; o <= 2; o <<= 1)
#pragma unroll
        for (int mi = 0; mi < 2; mi++)
#pragma unroll
            for (int h = 0; h < 2; h++) {
                s[mi][h] += __shfl_xor_sync(0xffffffffu, s[mi][h], o);
                q[mi][h] += __shfl_xor_sync(0xffffffffu, q[mi][h], o);
            }
    if ((lane & 3) == 0) {
#pragma unroll
        for (int mi = 0; mi < 2; mi++)
#pragma unroll
            for (int h = 0; h < 2; h++) {
                int r = m0 + mi * 16 + r0l + 8 * h;
                sRed[wn][r][0] = s[mi][h];
                sRed[wn][r][1] = q[mi][h];
            }
    }
    __syncthreads();
    float mu[2][2], rs[2][2];
#pragma unroll
    for (int mi = 0; mi < 2; mi++)
#pragma unroll
        for (int h = 0; h < 2; h++) {
            int r = m0 + mi * 16 + r0l + 8 * h;
            float S = sRed[0][r][0] + sRed[1][r][0];
            float Q = sRed[0][r][1] + sRed[1][r][1];
            float m = S * (1.f / HD);
            float var = Q * (1.f / HD) - m * m;
            mu[mi][h] = m;
            rs[mi][h] = rsqrtf(var + LN_EPS);
        }
    float* so = (float*)(sm + 73728u);  // stride 130, 256 rows = 133120 B
#pragma unroll
    for (int mi = 0; mi < 2; mi++)
#pragma unroll
        for (int j = 0; j < 8; j++) {
            int c = n0 + j * 8 + cq;
            float b0 = bias[c], b1 = bias[c + 1];
            float g0 = gam[c], g1 = gam[c + 1];
            float e0 = bet[c], e1 = bet[c + 1];
#pragma unroll
            for (int h = 0; h < 2; h++) {
                int r = m0 + mi * 16 + r0l + 8 * h;
                float v0 = acc[mi][j][2 * h] + b0;
                float v1 = acc[mi][j][2 * h + 1] + b1;
                so[r * 130 + c]     = (v0 - mu[mi][h]) * rs[mi][h] * g0 + e0;
                so[r * 130 + c + 1] = (v1 - mu[mi][h]) * rs[mi][h] * g1 + e1;
            }
        }
}

// ================= fused MLP kernel (512 threads, M=256, pipelined) =================
template <int MODE, int NCH, int K16S1>
__global__ __launch_bounds__(512, 1) void mma_mlp(
    const float* __restrict__ in0, const float* __restrict__ in1,
    int o1, int o2, int o3, int Kpad1,
    const float* __restrict__ b1, const float* __restrict__ b2,
    const float* __restrict__ b3, const float* __restrict__ gam,
    const float* __restrict__ bet,
    const float* __restrict__ resid, float* __restrict__ out, int rows) {
    extern __shared__ char sm[];
    __shared__ float sRed[2][ROWS_CTA][2];
    const int t = threadIdx.x;
    const uint32_t sb = smem_u32(sm);
    const int lane = t & 31, w = t >> 5;
    const int m0 = (w & 7) * 32, n0 = (w >> 3) * 64, wn = w >> 3;
    const int row0 = blockIdx.x * ROWS_CTA;
    float acc[2][8][4];
    float4 v[4];

    // ---- layer 1: pipelined 64-col chunks ----
    zero_acc(acc);
    for (int c = 0; c < NCH; c++) {
        __syncthreads();                         // SL(c&1), WB(c&1) free
        a_load<MODE>(in0, in1, c, 0, row0, rows, t, v);
        a_store((char*)sm, SL(c & 1), 0, t, v);
        a_load<MODE>(in0, in1, c, 1, row0, rows, t, v);
        a_store((char*)sm, SL(c & 1), 1, t, v);
        load_w_async(sb, WB(c & 1), o1, c * 64, Kpad1, t);
        CP_COMMIT();
        if (c > 0) mma_chunk<K16S1>(sb, SL((c - 1) & 1), WB((c - 1) & 1), acc, m0, n0, lane);
        CP_WAIT0();
    }
    __syncthreads();
    mma_chunk<K16S1>(sb, SL((NCH - 1) & 1), WB((NCH - 1) & 1), acc, m0, n0, lane);
    __syncthreads();

    // ---- layer 2 ----
    load_w_async(sb, WB(0), o2, 0, 128, t);
    load_w_async(sb, WB(1), o2, 64, 128, t);
    CP_COMMIT();
    epi_silu((char*)sm, acc, b1, m0, n0, lane);
    zero_acc(acc);
    CP_WAIT0();
    __syncthreads();
    mma_chunk<4>(sb, SL(0), WB(0), acc, m0, n0, lane);
    mma_chunk<4>(sb, SL(1), WB(1), acc, m0, n0, lane);
    __syncthreads();

    // ---- layer 3 ----
    load_w_async(sb, WB(0), o3, 0, 128, t);
    load_w_async(sb, WB(1), o3, 64, 128, t);
    CP_COMMIT();
    epi_silu((char*)sm, acc, b2, m0, n0, lane);
    zero_acc(acc);
    CP_WAIT0();
    __syncthreads();
    mma_chunk<4>(sb, SL(0), WB(0), acc, m0, n0, lane);
    mma_chunk<4>(sb, SL(1), WB(1), acc, m0, n0, lane);
    __syncthreads();
    epi_ln((char*)sm, acc, b3, gam, bet, sRed, m0, n0, wn, lane);
    __syncthreads();

    // ---- residual + coalesced store ----
    const float* so = (const float*)(sm + 73728u);
    const int col = t & 127;
    for (int r = (t >> 7); r < ROWS_CTA; r += 4) {
        int row = row0 + r;
        if (row < rows) {
            float y = so[r * 130 + col];
            if (MODE != 0) y += resid[(size_t)row * HD + col];
            out[(size_t)row * HD + col] = y;
        }
    }
}

// ================= aggregation =================
__global__ void zero_agg_kernel() {
    size_t i = (size_t)blockIdx.x * blockDim.x + threadIdx.x;
    if (i < (size_t)NN * HD) g_agg[i] = 0.f;
}
__global__ void scatter_kernel(const float* __restrict__ e) {
    size_t i = (size_t)blockIdx.x * blockDim.x + threadIdx.x;
    if (i >= (size_t)NE * (HD / 4)) return;
    int edge = (int)(i >> 5);
    int c = (int)(i & 31) << 2;
    float4 val = *(const float4*)(e + (size_t)edge * HD + c);
    float* p = g_agg + (size_t)g_dst[edge] * HD + c;
    asm volatile("red.global.add.v4.f32 [%0], {%1, %2, %3, %4};"
                 :: "l"(p), "f"(val.x), "f"(val.y), "f"(val.z), "f"(val.w)
                 : "memory");
}

// ================= launch =================
extern "C" void kernel_launch(void* const* d_in, const int* in_sizes, int n_in,
                              void* d_out, int out_size) {
    const float* x_in    = (const float*)d_in[0];
    const int*   eidx    = (const int*)d_in[1];
    const float* eattr   = (const float*)d_in[2];
    const float* emb_W1  = (const float*)d_in[3];
    const float* emb_b1  = (const float*)d_in[4];
    const float* emb_W2  = (const float*)d_in[5];
    const float* emb_b2  = (const float*)d_in[6];
    const float* emb_W3  = (const float*)d_in[7];
    const float* emb_b3  = (const float*)d_in[8];
    const float* emb_g   = (const float*)d_in[9];
    const float* emb_be  = (const float*)d_in[10];
    const float* edge_W1 = (const float*)d_in[11];
    const float* edge_b1 = (const float*)d_in[12];
    const float* edge_W2 = (const float*)d_in[13];
    const float* edge_b2 = (const float*)d_in[14];
    const float* edge_W3 = (const float*)d_in[15];
    const float* edge_b3 = (const float*)d_in[16];
    const float* edge_g  = (const float*)d_in[17];
    const float* edge_be = (const float*)d_in[18];
    const float* node_W1 = (const float*)d_in[19];
    const float* node_b1 = (const float*)d_in[20];
    const float* node_W2 = (const float*)d_in[21];
    const float* node_b2 = (const float*)d_in[22];
    const float* node_W3 = (const float*)d_in[23];
    const float* node_b3 = (const float*)d_in[24];
    const float* node_g  = (const float*)d_in[25];
    const float* node_be = (const float*)d_in[26];

    float* out_x = (float*)d_out;
    float* out_e = (float*)d_out + (size_t)NN * HD;

    float *eA, *eB, *agg, *xbuf;
    cudaGetSymbolAddress((void**)&eA, g_eA);
    cudaGetSymbolAddress((void**)&eB, g_eB);
    cudaGetSymbolAddress((void**)&agg, g_agg);
    cudaGetSymbolAddress((void**)&xbuf, g_x);

    cudaFuncSetAttribute((const void*)mma_mlp<0, 1, 1>, cudaFuncAttributeMaxDynamicSharedMemorySize, SMEM_DYN);
    cudaFuncSetAttribute((const void*)mma_mlp<1, 6, 4>, cudaFuncAttributeMaxDynamicSharedMemorySize, SMEM_DYN);
    cudaFuncSetAttribute((const void*)mma_mlp<2, 4, 4>, cudaFuncAttributeMaxDynamicSharedMemorySize, SMEM_DYN);

    // index prep (clamped)
    detect_kernel<<<1, 256>>>(eidx);
    convert_kernel<<<(NE + 255) / 256, 256>>>(eidx);

    // pool offsets (elements)
    const int oEmb1 = 0, oEmb2 = 8192, oEmb3 = 24576;
    int oE1[2], oE2[2], oE3[2], oN1[2], oN2[2], oN3[2];
    int base = 40960;
    for (int l = 0; l < 2; l++) {
        oE1[l] = base;
        oE2[l] = base + 49152;
        oE3[l] = base + 65536;
        oN1[l] = base + 81920;
        oN2[l] = base + 114688;
        oN3[l] = base + 131072;
        base += 147456;
    }

    WJobs jobs;
    int ji = 0;
    jobs.j[ji++] = {emb_W1, 16, 16, oEmb1};
    jobs.j[ji++] = {emb_W2, 128, 128, oEmb2};
    jobs.j[ji++] = {emb_W3, 128, 128, oEmb3};
    for (int l = 0; l < 2; l++) {
        jobs.j[ji++] = {edge_W1 + (size_t)l * 3 * HD * HD, 384, 384, oE1[l]};
        jobs.j[ji++] = {edge_W2 + (size_t)l * HD * HD, 128, 128, oE2[l]};
        jobs.j[ji++] = {edge_W3 + (size_t)l * HD * HD, 128, 128, oE3[l]};
        jobs.j[ji++] = {node_W1 + (size_t)l * 2 * HD * HD, 256, 256, oN1[l]};
        jobs.j[ji++] = {node_W2 + (size_t)l * HD * HD, 128, 128, oN2[l]};
        jobs.j[ji++] = {node_W3 + (size_t)l * HD * HD, 128, 128, oN3[l]};
    }
    dim3 cg((128 * 384 + 255) / 256, NJOBS);
    conv_w_kernel<<<cg, 256>>>(jobs);

    const int edge_blocks = (NE + ROWS_CTA - 1) / ROWS_CTA;   // 1563
    const int node_blocks = (NN + ROWS_CTA - 1) / ROWS_CTA;   // 98
    const int scat_blocks = (int)(((size_t)NE * (HD / 4) + 255) / 256);
    const int nthr_blocks = (int)(((size_t)NN * HD + 255) / 256);

    // edge embedding: e = MLP(edge_attr)
    mma_mlp<0, 1, 1><<<edge_blocks, 512, SMEM_DYN>>>(
        eattr, nullptr, oEmb1, oEmb2, oEmb3, 16,
        emb_b1, emb_b2, emb_b3, emb_g, emb_be, nullptr, eA, NE);

    const float* x_cur = x_in;
    float* e_cur = eA;
    for (int l = 0; l < 2; l++) {
        float* e_out = (l == 0) ? eB : out_e;
        float* x_out = (l == 0) ? xbuf : out_x;

        // e_new = MLP([x[dst] | x[src] | e]) + e
        mma_mlp<1, 6, 4><<<edge_blocks, 512, SMEM_DYN>>>(
            x_cur, e_cur, oE1[l], oE2[l], oE3[l], 384,
            edge_b1 + l * HD, edge_b2 + l * HD, edge_b3 + l * HD,
            edge_g + l * HD, edge_be + l * HD, e_cur, e_out, NE);

        // agg = segment_sum(e_new, dst)
        zero_agg_kernel<<<nthr_blocks, 256>>>();
        scatter_kernel<<<scat_blocks, 256>>>(e_out);

        // x = MLP([x | agg]) + x
        mma_mlp<2, 4, 4><<<node_blocks, 512, SMEM_DYN>>>(
            x_cur, agg, oN1[l], oN2[l], oN3[l], 256,
            node_b1 + l * HD, node_b2 + l * HD, node_b3 + l * HD,
            node_g + l * HD, node_be + l * HD, x_cur, x_out, NN);

        e_cur = e_out;
        x_cur = x_out;
    }
}